// round 5
// baseline (speedup 1.0000x reference)
#include <cuda_runtime.h>
#include <stdint.h>

#define NN 100000
#define NE 1200000
#define SCAN_B 1024
#define NBLK ((NN + SCAN_B - 1) / SCAN_B)   // 98

// ---------------- scratch (device globals: allocation-free) ----------------
__device__ __align__(128) float g_h[NN * 64];     // dinv-scaled GEMM output
__device__ __align__(128) float g_out[NN * 64];   // aggregation output
__device__ __align__(128) float g_dinv[NN];
__device__ __align__(128) int   g_cnt[NN];        // in-degree (excl. self)
__device__ __align__(128) int   g_rowptr[NN + 1];
__device__ __align__(128) int   g_wpos[NN];
__device__ __align__(128) int   g_row[NE];
__device__ __align__(128) int   g_col[NE];
__device__ __align__(128) int   g_src[NE];        // CSR: sources grouped by dst
__device__ __align__(128) int   g_tmp[NN];
__device__ __align__(128) int   g_bsum[NBLK];
__device__ int g_is64;                             // edge_index dtype flag

// ---------------- dtype probe: int32 vs int64 edge_index -------------------
// If edge_index is int64 (little-endian, values < 2^31), every odd int32 slot
// among the first 64 is zero. Random int32 indices make that astronomically
// unlikely. Deterministic given the input.
__global__ void k_probe(const int* __restrict__ ei) {
    if (threadIdx.x == 0) {
        int all_zero = 1;
        for (int i = 0; i < 32; i++)
            if (ei[2 * i + 1] != 0) { all_zero = 0; break; }
        g_is64 = all_zero;
    }
}

// ---------------- CSR build ----------------
__global__ void k_zero() {
    int i = blockIdx.x * blockDim.x + threadIdx.x;
    if (i < NN) g_cnt[i] = 0;
}

__global__ void k_edges(const int* __restrict__ ei) {
    int e = blockIdx.x * blockDim.x + threadIdx.x;
    if (e < NE) {
        int stride = g_is64 ? 2 : 1;            // int64: low word at 2*idx
        int r = ei[(size_t)e * stride];
        int c = ei[(size_t)(NE + e) * stride];
        r = min(max(r, 0), NN - 1);             // never trap on bad input
        c = min(max(c, 0), NN - 1);
        g_row[e] = r;
        g_col[e] = c;
        atomicAdd(&g_cnt[c], 1);
    }
}

__global__ void k_scanA() {
    __shared__ int sm[SCAN_B];
    int i = blockIdx.x * SCAN_B + threadIdx.x;
    int v = (i < NN) ? g_cnt[i] : 0;
    sm[threadIdx.x] = v;
    __syncthreads();
    for (int off = 1; off < SCAN_B; off <<= 1) {
        int t = (threadIdx.x >= off) ? sm[threadIdx.x - off] : 0;
        __syncthreads();
        sm[threadIdx.x] += t;
        __syncthreads();
    }
    if (i < NN) g_tmp[i] = sm[threadIdx.x];
    if (threadIdx.x == SCAN_B - 1) g_bsum[blockIdx.x] = sm[threadIdx.x];
}

__global__ void k_scanB() {
    if (threadIdx.x == 0) {
        int run = 0;
        for (int b = 0; b < NBLK; b++) {
            int t = g_bsum[b];
            g_bsum[b] = run;
            run += t;
        }
    }
}

__global__ void k_scanC() {
    int i = blockIdx.x * SCAN_B + threadIdx.x;
    if (i < NN) {
        int inc = g_tmp[i] + g_bsum[blockIdx.x];
        g_rowptr[i + 1] = inc;
        g_wpos[i] = inc - g_cnt[i];
        g_dinv[i] = rsqrtf((float)(g_cnt[i] + 1));   // +1 self-loop
    }
    if (i == 0) g_rowptr[0] = 0;
}

__global__ void k_fill() {
    int e = blockIdx.x * blockDim.x + threadIdx.x;
    if (e < NE) {
        int pos = atomicAdd(&g_wpos[g_col[e]], 1);
        g_src[pos] = g_row[e];
    }
}

// ---------------- GEMM: g_h[row] = dinv[row] * (act(in + b_prev) @ W) ------
// Warp per row; W in smem; x row in registers, broadcast via shfl.
template <int DIN, int DOUT, bool ACT, bool FROMG>
__global__ void k_gemm(const float* __restrict__ in_ext,
                       const float* __restrict__ b_prev,
                       const float* __restrict__ W) {
    __shared__ float Ws[DIN * DOUT];
    for (int i = threadIdx.x; i < DIN * DOUT; i += blockDim.x) Ws[i] = W[i];
    __syncthreads();

    const int lane = threadIdx.x & 31;
    const int wid  = threadIdx.x >> 5;
    const int row  = blockIdx.x * (blockDim.x >> 5) + wid;
    if (row >= NN) return;

    const float* in = FROMG ? g_out : in_ext;

    constexpr int NX = DIN / 32;
    constexpr int NA = DOUT / 32;

    float xv[NX];
#pragma unroll
    for (int i = 0; i < NX; i++) {
        float v = in[row * DIN + i * 32 + lane];
        if (ACT) v = fmaxf(v + b_prev[i * 32 + lane], 0.0f);
        xv[i] = v;
    }

    float acc[NA];
#pragma unroll
    for (int j = 0; j < NA; j++) acc[j] = 0.0f;

#pragma unroll
    for (int k = 0; k < DIN; k++) {
        float xk = __shfl_sync(0xffffffffu, xv[k >> 5], k & 31);
#pragma unroll
        for (int j = 0; j < NA; j++)
            acc[j] = fmaf(xk, Ws[k * DOUT + j * 32 + lane], acc[j]);
    }

    float d = g_dinv[row];
#pragma unroll
    for (int j = 0; j < NA; j++)
        g_h[row * DOUT + j * 32 + lane] = d * acc[j];
}

// ---------------- aggregate: g_out[n] = dinv[n]*(g_h[n] + sum_src g_h[src]) -
// GRP = DOUT/4 threads per node, each owning one float4 chunk. No atomics.
template <int DOUT>
__global__ void k_aggregate() {
    constexpr int GRP = DOUT / 4;
    int t = blockIdx.x * blockDim.x + threadIdx.x;
    int n = t / GRP;
    int g = t % GRP;
    if (n >= NN) return;

    const float4* __restrict__ h4 = reinterpret_cast<const float4*>(g_h);

    float4 acc = h4[n * GRP + g];           // self term (h pre-scaled by dinv)
    int beg = g_rowptr[n];
    int end = g_rowptr[n + 1];
    int e = beg;
    for (; e + 4 <= end; e += 4) {
        int s0 = g_src[e], s1 = g_src[e + 1], s2 = g_src[e + 2], s3 = g_src[e + 3];
        float4 a = h4[s0 * GRP + g];
        float4 b = h4[s1 * GRP + g];
        float4 c = h4[s2 * GRP + g];
        float4 d = h4[s3 * GRP + g];
        acc.x += a.x + b.x + c.x + d.x;
        acc.y += a.y + b.y + c.y + d.y;
        acc.z += a.z + b.z + c.z + d.z;
        acc.w += a.w + b.w + c.w + d.w;
    }
    for (; e < end; e++) {
        float4 a = h4[g_src[e] * GRP + g];
        acc.x += a.x; acc.y += a.y; acc.z += a.z; acc.w += a.w;
    }

    float dn = g_dinv[n];
    float4 o;
    o.x = dn * acc.x; o.y = dn * acc.y; o.z = dn * acc.z; o.w = dn * acc.w;
    reinterpret_cast<float4*>(g_out)[n * GRP + g] = o;
}

// ---------------- final: add b3, L2-normalize rows, write d_out ------------
__global__ void k_final(const float* __restrict__ b, float* __restrict__ out) {
    const int lane = threadIdx.x & 31;
    const int wid  = threadIdx.x >> 5;
    const int row  = blockIdx.x * (blockDim.x >> 5) + wid;
    if (row >= NN) return;

    float v0 = g_out[row * 64 + lane]      + b[lane];
    float v1 = g_out[row * 64 + 32 + lane] + b[32 + lane];
    float s = v0 * v0 + v1 * v1;
#pragma unroll
    for (int off = 16; off; off >>= 1) s += __shfl_xor_sync(0xffffffffu, s, off);
    float inv = 1.0f / fmaxf(sqrtf(s), 1e-12f);
    out[row * 64 + lane]      = v0 * inv;
    out[row * 64 + 32 + lane] = v1 * inv;
}

// ---------------- launch ----------------
extern "C" void kernel_launch(void* const* d_in, const int* in_sizes, int n_in,
                              void* d_out, int out_size) {
    const float* x  = (const float*)d_in[0];
    const int*   ei = (const int*)d_in[1];     // int32 (JAX x64 disabled) or int64 via probe
    const float* W1 = (const float*)d_in[2];
    const float* b1 = (const float*)d_in[3];
    const float* W2 = (const float*)d_in[4];
    const float* b2 = (const float*)d_in[5];
    const float* W3 = (const float*)d_in[6];
    const float* b3 = (const float*)d_in[7];
    float* out = (float*)d_out;

    const int TB = 256;
    const int NODE_BLKS = (NN + TB - 1) / TB;
    const int EDGE_BLKS = (NE + TB - 1) / TB;
    const int GEMM_BLKS = (NN + 7) / 8;          // 8 warps (rows) per block

    // dtype probe + CSR + dinv (shared by all 3 layers)
    k_probe<<<1, 32>>>(ei);
    k_zero <<<NODE_BLKS, TB>>>();
    k_edges<<<EDGE_BLKS, TB>>>(ei);
    k_scanA<<<NBLK, SCAN_B>>>();
    k_scanB<<<1, 32>>>();
    k_scanC<<<NBLK, SCAN_B>>>();
    k_fill <<<EDGE_BLKS, TB>>>();

    // Layer 1: 64 -> 32
    k_gemm<64, 32, false, false><<<GEMM_BLKS, TB>>>(x, nullptr, W1);
    k_aggregate<32><<<(NN * 8 + TB - 1) / TB, TB>>>();

    // Layer 2: 32 -> 64 (fused +b1, relu)
    k_gemm<32, 64, true, true><<<GEMM_BLKS, TB>>>(x, b1, W2);
    k_aggregate<64><<<(NN * 16 + TB - 1) / TB, TB>>>();

    // Layer 3: 64 -> 64 (fused +b2, relu)
    k_gemm<64, 64, true, true><<<GEMM_BLKS, TB>>>(x, b2, W3);
    k_aggregate<64><<<(NN * 16 + TB - 1) / TB, TB>>>();

    // Final: +b3, row L2-normalize
    k_final<<<GEMM_BLKS, TB>>>(b3, out);
}

// round 6
// speedup vs baseline: 1.1498x; 1.1498x over previous
#include <cuda_runtime.h>
#include <stdint.h>

#define NN 100000
#define NE 1200000
#define SCAN_B 1024
#define NBLK ((NN + SCAN_B - 1) / SCAN_B)   // 98

// ---------------- scratch (device globals: allocation-free) ----------------
__device__ __align__(128) float g_hA[NN * 64];    // h ping
__device__ __align__(128) float g_hB[NN * 64];    // h pong
__device__ __align__(128) float g_dinv[NN];
__device__ __align__(128) int   g_cnt[NN];        // in-degree (excl. self)
__device__ __align__(128) int   g_rowptr[NN + 1];
__device__ __align__(128) int   g_wpos[NN];
__device__ __align__(128) int   g_row[NE];
__device__ __align__(128) int   g_col[NE];
__device__ __align__(128) int   g_src[NE];        // CSR: sources grouped by dst
__device__ __align__(128) int   g_tmp[NN];
__device__ __align__(128) int   g_bsum[NBLK];
__device__ int g_is64;                            // edge_index dtype flag

// ---------------- init: zero counters + dtype probe ----------------
// int64 little-endian with values < 2^31 => every odd int32 word of the first
// 64 is zero; astronomically unlikely for random int32 indices.
__global__ void k_init(const int* __restrict__ ei) {
    int i = blockIdx.x * blockDim.x + threadIdx.x;
    if (i < NN) g_cnt[i] = 0;
    if (i == 0) {
        int all_zero = 1;
        for (int j = 0; j < 32; j++)
            if (ei[2 * j + 1] != 0) { all_zero = 0; break; }
        g_is64 = all_zero;
    }
}

__global__ void k_edges(const int* __restrict__ ei) {
    int e = blockIdx.x * blockDim.x + threadIdx.x;
    if (e < NE) {
        int stride = g_is64 ? 2 : 1;
        int r = ei[(size_t)e * stride];
        int c = ei[(size_t)(NE + e) * stride];
        r = min(max(r, 0), NN - 1);               // never trap on bad input
        c = min(max(c, 0), NN - 1);
        g_row[e] = r;
        g_col[e] = c;
        atomicAdd(&g_cnt[c], 1);
    }
}

__global__ void k_scanA() {
    __shared__ int sm[SCAN_B];
    int i = blockIdx.x * SCAN_B + threadIdx.x;
    int v = (i < NN) ? g_cnt[i] : 0;
    sm[threadIdx.x] = v;
    __syncthreads();
    for (int off = 1; off < SCAN_B; off <<= 1) {
        int t = (threadIdx.x >= off) ? sm[threadIdx.x - off] : 0;
        __syncthreads();
        sm[threadIdx.x] += t;
        __syncthreads();
    }
    if (i < NN) g_tmp[i] = sm[threadIdx.x];
    if (threadIdx.x == SCAN_B - 1) g_bsum[blockIdx.x] = sm[threadIdx.x];
}

__global__ void k_scanB() {
    if (threadIdx.x == 0) {
        int run = 0;
        for (int b = 0; b < NBLK; b++) {
            int t = g_bsum[b];
            g_bsum[b] = run;
            run += t;
        }
    }
}

__global__ void k_scanC() {
    int i = blockIdx.x * SCAN_B + threadIdx.x;
    if (i < NN) {
        int inc = g_tmp[i] + g_bsum[blockIdx.x];
        g_rowptr[i + 1] = inc;
        g_wpos[i] = inc - g_cnt[i];
        g_dinv[i] = rsqrtf((float)(g_cnt[i] + 1));   // +1 self-loop
    }
    if (i == 0) g_rowptr[0] = 0;
}

__global__ void k_fill() {
    int e = blockIdx.x * blockDim.x + threadIdx.x;
    if (e < NE) {
        int pos = atomicAdd(&g_wpos[g_col[e]], 1);
        g_src[pos] = g_row[e];
    }
}

// ---------------- layer-1 GEMM: g_hA[row] = dinv[row] * (x @ W1) -----------
// Warp per row; W in smem; x row in registers, broadcast via shfl.
__global__ void k_gemm1(const float* __restrict__ x, const float* __restrict__ W,
                        float* __restrict__ hout) {
    __shared__ float Ws[64 * 32];
    for (int i = threadIdx.x; i < 64 * 32; i += blockDim.x) Ws[i] = W[i];
    __syncthreads();

    const int lane = threadIdx.x & 31;
    const int wid  = threadIdx.x >> 5;
    const int row  = blockIdx.x * (blockDim.x >> 5) + wid;
    if (row >= NN) return;

    float xv0 = x[row * 64 + lane];
    float xv1 = x[row * 64 + 32 + lane];

    float acc = 0.0f;
#pragma unroll
    for (int k = 0; k < 32; k++)
        acc = fmaf(__shfl_sync(0xffffffffu, xv0, k), Ws[k * 32 + lane], acc);
#pragma unroll
    for (int k = 0; k < 32; k++)
        acc = fmaf(__shfl_sync(0xffffffffu, xv1, k), Ws[(32 + k) * 32 + lane], acc);

    hout[row * 32 + lane] = g_dinv[row] * acc;
}

// ---------------- fused aggregate + next-layer GEMM ------------------------
// o[n] = dinv[n]*(h[n] + sum_src h[src]); z = relu(o + bprev);
// hout[n] = dinv[n] * (z @ W).   GRP = HD/4 threads per node.
template <int HD, int DN>
__global__ void k_agg_gemm(const float* __restrict__ hin,
                           float* __restrict__ hout,
                           const float* __restrict__ bprev,
                           const float* __restrict__ W) {
    constexpr int GRP = HD / 4;          // threads per node (8 or 16)
    constexpr int NPW = 32 / GRP;        // nodes per warp
    constexpr int CPT = DN / GRP;        // output cols per thread (8 or 4)
    constexpr int XST = HD + 4;          // padded smem row stride (floats)

    __shared__ float Ws[HD * DN];
    __shared__ float xsh[8 * NPW * XST];

    for (int i = threadIdx.x; i < HD * DN; i += blockDim.x) Ws[i] = W[i];
    __syncthreads();

    const int t = blockIdx.x * blockDim.x + threadIdx.x;   // grid sized exactly
    const int n = t / GRP;
    const int g = t % GRP;

    const float4* __restrict__ h4 = reinterpret_cast<const float4*>(hin);

    // ---- gather (memory-bound phase) ----
    float4 acc = h4[n * GRP + g];                 // self term (h pre-scaled)
    int e = g_rowptr[n], end = g_rowptr[n + 1];
    for (; e + 4 <= end; e += 4) {
        int s0 = g_src[e], s1 = g_src[e + 1], s2 = g_src[e + 2], s3 = g_src[e + 3];
        float4 a = h4[s0 * GRP + g];
        float4 b = h4[s1 * GRP + g];
        float4 c = h4[s2 * GRP + g];
        float4 d = h4[s3 * GRP + g];
        acc.x += a.x + b.x + c.x + d.x;
        acc.y += a.y + b.y + c.y + d.y;
        acc.z += a.z + b.z + c.z + d.z;
        acc.w += a.w + b.w + c.w + d.w;
    }
    for (; e < end; e++) {
        float4 a = h4[g_src[e] * GRP + g];
        acc.x += a.x; acc.y += a.y; acc.z += a.z; acc.w += a.w;
    }

    const float dn = g_dinv[n];
    const float4 bp = reinterpret_cast<const float4*>(bprev)[g];
    float4 z;
    z.x = fmaxf(fmaf(dn, acc.x, bp.x), 0.0f);
    z.y = fmaxf(fmaf(dn, acc.y, bp.y), 0.0f);
    z.z = fmaxf(fmaf(dn, acc.z, bp.z), 0.0f);
    z.w = fmaxf(fmaf(dn, acc.w, bp.w), 0.0f);

    // ---- stage row in smem (warp-local), then GEMM (compute phase) ----
    const int wid = threadIdx.x >> 5;
    const int nw  = (threadIdx.x & 31) / GRP;
    float* xrow = &xsh[(wid * NPW + nw) * XST];
    reinterpret_cast<float4*>(xrow)[g] = z;
    __syncwarp();

    float out[CPT];
#pragma unroll
    for (int j = 0; j < CPT; j++) out[j] = 0.0f;

#pragma unroll
    for (int k4 = 0; k4 < HD / 4; k4++) {
        float4 xk = reinterpret_cast<const float4*>(xrow)[k4];
        const float* wr = &Ws[(k4 * 4) * DN + g * CPT];
#pragma unroll
        for (int kk = 0; kk < 4; kk++) {
            float xv = (&xk.x)[kk];
#pragma unroll
            for (int j = 0; j < CPT; j++)
                out[j] = fmaf(xv, wr[kk * DN + j], out[j]);
        }
    }

#pragma unroll
    for (int j = 0; j < CPT; j += 4) {
        float4 o;
        o.x = dn * out[j];     o.y = dn * out[j + 1];
        o.z = dn * out[j + 2]; o.w = dn * out[j + 3];
        reinterpret_cast<float4*>(hout)[(n * DN + g * CPT + j) >> 2] = o;
    }
}

// ---------------- fused aggregate + bias + row L2-normalize ----------------
__global__ void k_agg_final(const float* __restrict__ hin,
                            const float* __restrict__ b3,
                            float* __restrict__ out) {
    const int t = blockIdx.x * blockDim.x + threadIdx.x;
    const int n = t >> 4;          // GRP = 16
    const int g = t & 15;

    const float4* __restrict__ h4 = reinterpret_cast<const float4*>(hin);

    float4 acc = h4[n * 16 + g];
    int e = g_rowptr[n], end = g_rowptr[n + 1];
    for (; e + 4 <= end; e += 4) {
        int s0 = g_src[e], s1 = g_src[e + 1], s2 = g_src[e + 2], s3 = g_src[e + 3];
        float4 a = h4[s0 * 16 + g];
        float4 b = h4[s1 * 16 + g];
        float4 c = h4[s2 * 16 + g];
        float4 d = h4[s3 * 16 + g];
        acc.x += a.x + b.x + c.x + d.x;
        acc.y += a.y + b.y + c.y + d.y;
        acc.z += a.z + b.z + c.z + d.z;
        acc.w += a.w + b.w + c.w + d.w;
    }
    for (; e < end; e++) {
        float4 a = h4[g_src[e] * 16 + g];
        acc.x += a.x; acc.y += a.y; acc.z += a.z; acc.w += a.w;
    }

    const float dn = g_dinv[n];
    const float4 bp = reinterpret_cast<const float4*>(b3)[g];
    float4 v;
    v.x = fmaf(dn, acc.x, bp.x);
    v.y = fmaf(dn, acc.y, bp.y);
    v.z = fmaf(dn, acc.z, bp.z);
    v.w = fmaf(dn, acc.w, bp.w);

    float s = v.x * v.x + v.y * v.y + v.z * v.z + v.w * v.w;
    // 16-lane group reduction: xor offsets < 16 stay within the group
    s += __shfl_xor_sync(0xffffffffu, s, 1);
    s += __shfl_xor_sync(0xffffffffu, s, 2);
    s += __shfl_xor_sync(0xffffffffu, s, 4);
    s += __shfl_xor_sync(0xffffffffu, s, 8);
    float inv = 1.0f / fmaxf(sqrtf(s), 1e-12f);

    float4 o;
    o.x = v.x * inv; o.y = v.y * inv; o.z = v.z * inv; o.w = v.w * inv;
    reinterpret_cast<float4*>(out)[n * 16 + g] = o;
}

// ---------------- launch ----------------
extern "C" void kernel_launch(void* const* d_in, const int* in_sizes, int n_in,
                              void* d_out, int out_size) {
    const float* x  = (const float*)d_in[0];
    const int*   ei = (const int*)d_in[1];   // int32 (JAX x64 off) or int64 via probe
    const float* W1 = (const float*)d_in[2];
    const float* b1 = (const float*)d_in[3];
    const float* W2 = (const float*)d_in[4];
    const float* b2 = (const float*)d_in[5];
    const float* W3 = (const float*)d_in[6];
    const float* b3 = (const float*)d_in[7];
    float* out = (float*)d_out;

    float *hA, *hB;
    cudaGetSymbolAddress((void**)&hA, g_hA);
    cudaGetSymbolAddress((void**)&hB, g_hB);

    const int TB = 256;
    const int NODE_BLKS = (NN + TB - 1) / TB;
    const int EDGE_BLKS = (NE + TB - 1) / TB;

    // CSR + dinv (shared by all 3 layers)
    k_init <<<NODE_BLKS, TB>>>(ei);
    k_edges<<<EDGE_BLKS, TB>>>(ei);
    k_scanA<<<NBLK, SCAN_B>>>();
    k_scanB<<<1, 32>>>();
    k_scanC<<<NBLK, SCAN_B>>>();
    k_fill <<<EDGE_BLKS, TB>>>();

    // Layer 1 GEMM: hA = dinv * (x @ W1)            [100000 rows, 8 warps/blk]
    k_gemm1<<<(NN + 7) / 8, TB>>>(x, W1, hA);

    // Layer 1 aggregate + Layer 2 GEMM: hB = dinv * (relu(agg(hA)+b1) @ W2)
    k_agg_gemm<32, 64><<<NN * 8 / TB, TB>>>(hA, hB, b1, W2);    // 3125 blocks

    // Layer 2 aggregate + Layer 3 GEMM: hA = dinv * (relu(agg(hB)+b2) @ W3)
    k_agg_gemm<64, 64><<<NN * 16 / TB, TB>>>(hB, hA, b2, W3);   // 6250 blocks

    // Layer 3 aggregate + b3 + row L2-normalize -> out
    k_agg_final<<<NN * 16 / TB, TB>>>(hA, b3, out);             // 6250 blocks
}

// round 7
// speedup vs baseline: 1.1872x; 1.0326x over previous
#include <cuda_runtime.h>
#include <stdint.h>

#define NN 100000
#define NE 1200000
#define SCAN_B 1024
#define NBLK ((NN + SCAN_B - 1) / SCAN_B)   // 98

// ---------------- scratch (device globals: allocation-free) ----------------
__device__ __align__(128) float g_hA[NN * 64];    // h ping
__device__ __align__(128) float g_hB[NN * 64];    // h pong
__device__ __align__(128) float g_dinv[NN];
__device__ __align__(128) int   g_cnt[NN];        // in-degree (excl. self)
__device__ __align__(128) int   g_rowptr[NN + 1];
__device__ __align__(128) int   g_wpos[NN];
__device__ __align__(128) int   g_src[NE];        // CSR: sources grouped by dst
__device__ __align__(128) int   g_tmp[NN];
__device__ __align__(128) int   g_bsum[NBLK];

// ---------------- per-block int64 probe (ei L2-cached => free) -------------
// int64 little-endian node ids < 2^31 => every odd int32 word of the first 64
// is zero; astronomically unlikely for random int32 ids.
__device__ __forceinline__ int probe_is64(const int* ei) {
    int az = 1;
#pragma unroll
    for (int j = 0; j < 32; j++) az &= (ei[2 * j + 1] == 0);
    return az;
}

// ---------------- count in-degrees (g_cnt pre-zeroed via memset) -----------
__global__ void k_edges(const int* __restrict__ ei) {
    __shared__ int s_is64;
    if (threadIdx.x == 0) s_is64 = probe_is64(ei);
    __syncthreads();
    int e = blockIdx.x * blockDim.x + threadIdx.x;
    if (e < NE) {
        int c = ei[(size_t)(NE + e) * (s_is64 ? 2 : 1)];
        c = min(max(c, 0), NN - 1);
        atomicAdd(&g_cnt[c], 1);
    }
}

// ---------------- scan pass A: block-local inclusive scan ------------------
__global__ void k_scanA() {
    __shared__ int sm[SCAN_B];
    int i = blockIdx.x * SCAN_B + threadIdx.x;
    int v = (i < NN) ? g_cnt[i] : 0;
    sm[threadIdx.x] = v;
    __syncthreads();
    for (int off = 1; off < SCAN_B; off <<= 1) {
        int t = (threadIdx.x >= off) ? sm[threadIdx.x - off] : 0;
        __syncthreads();
        sm[threadIdx.x] += t;
        __syncthreads();
    }
    if (i < NN) g_tmp[i] = sm[threadIdx.x];
    if (threadIdx.x == SCAN_B - 1) g_bsum[blockIdx.x] = sm[threadIdx.x];
}

// ---------------- scan pass B: inline block-sum scan + finalize ------------
__global__ void k_scanC() {
    __shared__ int bs[128];
    if (threadIdx.x < 128)
        bs[threadIdx.x] = (threadIdx.x < NBLK) ? g_bsum[threadIdx.x] : 0;
    __syncthreads();
    for (int off = 1; off < 128; off <<= 1) {
        int t = (threadIdx.x >= off && threadIdx.x < 128) ? bs[threadIdx.x - off] : 0;
        __syncthreads();
        if (threadIdx.x < 128) bs[threadIdx.x] += t;
        __syncthreads();
    }
    int base = (blockIdx.x == 0) ? 0 : bs[blockIdx.x - 1];

    int i = blockIdx.x * SCAN_B + threadIdx.x;
    if (i < NN) {
        int inc = g_tmp[i] + base;
        g_rowptr[i + 1] = inc;
        g_wpos[i] = inc - g_cnt[i];
        g_dinv[i] = rsqrtf((float)(g_cnt[i] + 1));   // +1 self-loop
    }
    if (i == 0) g_rowptr[0] = 0;
}

// ---------------- fused: CSR fill  +  layer-1 GEMM -------------------------
// Both depend only on scanC and are mutually independent: role split by block.
// fill:  g_src[pos(col)] = row      (random atomics, latency-bound)
// gemm1: hA[r] = dinv[r]*(x[r]@W1)  (FMA-bound)  -- warp per row, shfl bcast
__global__ void k_fill_gemm1(const int* __restrict__ ei, int fill_blocks,
                             const float* __restrict__ x,
                             const float* __restrict__ W,
                             float* __restrict__ hout) {
    if (blockIdx.x < fill_blocks) {
        __shared__ int s_is64;
        if (threadIdx.x == 0) s_is64 = probe_is64(ei);
        __syncthreads();
        int e = blockIdx.x * blockDim.x + threadIdx.x;
        if (e < NE) {
            int stride = s_is64 ? 2 : 1;
            int r = ei[(size_t)e * stride];
            int c = ei[(size_t)(NE + e) * stride];
            r = min(max(r, 0), NN - 1);
            c = min(max(c, 0), NN - 1);
            int pos = atomicAdd(&g_wpos[c], 1);
            g_src[pos] = r;
        }
        return;
    }

    __shared__ float Ws[64 * 32];
    for (int i = threadIdx.x; i < 64 * 32; i += blockDim.x) Ws[i] = W[i];
    __syncthreads();

    const int lane = threadIdx.x & 31;
    const int wid  = threadIdx.x >> 5;
    const int row  = (blockIdx.x - fill_blocks) * (blockDim.x >> 5) + wid;
    if (row >= NN) return;

    float xv0 = x[row * 64 + lane];
    float xv1 = x[row * 64 + 32 + lane];

    float acc = 0.0f;
#pragma unroll
    for (int k = 0; k < 32; k++)
        acc = fmaf(__shfl_sync(0xffffffffu, xv0, k), Ws[k * 32 + lane], acc);
#pragma unroll
    for (int k = 0; k < 32; k++)
        acc = fmaf(__shfl_sync(0xffffffffu, xv1, k), Ws[(32 + k) * 32 + lane], acc);

    hout[row * 32 + lane] = g_dinv[row] * acc;
}

// ---------------- fused aggregate + next-layer GEMM ------------------------
// o[n] = dinv[n]*(h[n] + sum_src h[src]); z = relu(o + bprev);
// hout[n] = dinv[n] * (z @ W).   GRP = HD/4 threads per node.
template <int HD, int DN>
__global__ void k_agg_gemm(const float* __restrict__ hin,
                           float* __restrict__ hout,
                           const float* __restrict__ bprev,
                           const float* __restrict__ W) {
    constexpr int GRP = HD / 4;          // threads per node (8 or 16)
    constexpr int NPW = 32 / GRP;        // nodes per warp
    constexpr int CPT = DN / GRP;        // output cols per thread (8 or 4)
    constexpr int XST = HD + 4;          // padded smem row stride (floats)

    __shared__ float Ws[HD * DN];
    __shared__ float xsh[8 * NPW * XST];

    for (int i = threadIdx.x; i < HD * DN; i += blockDim.x) Ws[i] = W[i];
    __syncthreads();

    const int t = blockIdx.x * blockDim.x + threadIdx.x;   // grid sized exactly
    const int n = t / GRP;
    const int g = t % GRP;

    const float4* __restrict__ h4 = reinterpret_cast<const float4*>(hin);

    // ---- gather (memory-bound): unroll 8 for MLP ----
    float4 acc = h4[n * GRP + g];                 // self term (h pre-scaled)
    int e = g_rowptr[n], end = g_rowptr[n + 1];
    for (; e + 8 <= end; e += 8) {
        int s[8];
#pragma unroll
        for (int u = 0; u < 8; u++) s[u] = g_src[e + u];
        float4 v[8];
#pragma unroll
        for (int u = 0; u < 8; u++) v[u] = h4[s[u] * GRP + g];
#pragma unroll
        for (int u = 0; u < 8; u++) {
            acc.x += v[u].x; acc.y += v[u].y; acc.z += v[u].z; acc.w += v[u].w;
        }
    }
    for (; e < end; e++) {
        float4 a = h4[g_src[e] * GRP + g];
        acc.x += a.x; acc.y += a.y; acc.z += a.z; acc.w += a.w;
    }

    const float dn = g_dinv[n];
    const float4 bp = reinterpret_cast<const float4*>(bprev)[g];
    float4 z;
    z.x = fmaxf(fmaf(dn, acc.x, bp.x), 0.0f);
    z.y = fmaxf(fmaf(dn, acc.y, bp.y), 0.0f);
    z.z = fmaxf(fmaf(dn, acc.z, bp.z), 0.0f);
    z.w = fmaxf(fmaf(dn, acc.w, bp.w), 0.0f);

    // ---- stage row in smem (warp-local), then GEMM (compute phase) ----
    const int wid = threadIdx.x >> 5;
    const int nw  = (threadIdx.x & 31) / GRP;
    float* xrow = &xsh[(wid * NPW + nw) * XST];
    reinterpret_cast<float4*>(xrow)[g] = z;
    __syncwarp();

    float out[CPT];
#pragma unroll
    for (int j = 0; j < CPT; j++) out[j] = 0.0f;

#pragma unroll
    for (int k4 = 0; k4 < HD / 4; k4++) {
        float4 xk = reinterpret_cast<const float4*>(xrow)[k4];
        const float* wr = &Ws[(k4 * 4) * DN + g * CPT];
#pragma unroll
        for (int kk = 0; kk < 4; kk++) {
            float xv = (&xk.x)[kk];
#pragma unroll
            for (int j = 0; j < CPT; j++)
                out[j] = fmaf(xv, wr[kk * DN + j], out[j]);
        }
    }

#pragma unroll
    for (int j = 0; j < CPT; j += 4) {
        float4 o;
        o.x = dn * out[j];     o.y = dn * out[j + 1];
        o.z = dn * out[j + 2]; o.w = dn * out[j + 3];
        reinterpret_cast<float4*>(hout)[(n * DN + g * CPT + j) >> 2] = o;
    }
}

// ---------------- fused aggregate + bias + row L2-normalize ----------------
__global__ void k_agg_final(const float* __restrict__ hin,
                            const float* __restrict__ b3,
                            float* __restrict__ out) {
    const int t = blockIdx.x * blockDim.x + threadIdx.x;
    const int n = t >> 4;          // GRP = 16
    const int g = t & 15;

    const float4* __restrict__ h4 = reinterpret_cast<const float4*>(hin);

    float4 acc = h4[n * 16 + g];
    int e = g_rowptr[n], end = g_rowptr[n + 1];
    for (; e + 8 <= end; e += 8) {
        int s[8];
#pragma unroll
        for (int u = 0; u < 8; u++) s[u] = g_src[e + u];
        float4 v[8];
#pragma unroll
        for (int u = 0; u < 8; u++) v[u] = h4[s[u] * 16 + g];
#pragma unroll
        for (int u = 0; u < 8; u++) {
            acc.x += v[u].x; acc.y += v[u].y; acc.z += v[u].z; acc.w += v[u].w;
        }
    }
    for (; e < end; e++) {
        float4 a = h4[g_src[e] * 16 + g];
        acc.x += a.x; acc.y += a.y; acc.z += a.z; acc.w += a.w;
    }

    const float dn = g_dinv[n];
    const float4 bp = reinterpret_cast<const float4*>(b3)[g];
    float4 v;
    v.x = fmaf(dn, acc.x, bp.x);
    v.y = fmaf(dn, acc.y, bp.y);
    v.z = fmaf(dn, acc.z, bp.z);
    v.w = fmaf(dn, acc.w, bp.w);

    float s = v.x * v.x + v.y * v.y + v.z * v.z + v.w * v.w;
    s += __shfl_xor_sync(0xffffffffu, s, 1);
    s += __shfl_xor_sync(0xffffffffu, s, 2);
    s += __shfl_xor_sync(0xffffffffu, s, 4);
    s += __shfl_xor_sync(0xffffffffu, s, 8);
    float inv = 1.0f / fmaxf(sqrtf(s), 1e-12f);

    float4 o;
    o.x = v.x * inv; o.y = v.y * inv; o.z = v.z * inv; o.w = v.w * inv;
    reinterpret_cast<float4*>(out)[n * 16 + g] = o;
}

// ---------------- launch ----------------
extern "C" void kernel_launch(void* const* d_in, const int* in_sizes, int n_in,
                              void* d_out, int out_size) {
    const float* x  = (const float*)d_in[0];
    const int*   ei = (const int*)d_in[1];   // int32 (JAX x64 off) or int64 via probe
    const float* W1 = (const float*)d_in[2];
    const float* b1 = (const float*)d_in[3];
    const float* W2 = (const float*)d_in[4];
    const float* b2 = (const float*)d_in[5];
    const float* W3 = (const float*)d_in[6];
    const float* b3 = (const float*)d_in[7];
    float* out = (float*)d_out;

    float *hA, *hB;
    cudaGetSymbolAddress((void**)&hA, g_hA);
    cudaGetSymbolAddress((void**)&hB, g_hB);
    int* cnt;
    cudaGetSymbolAddress((void**)&cnt, g_cnt);

    const int TB = 256;
    const int EDGE_BLKS = (NE + TB - 1) / TB;     // 4688
    const int GEMM_BLKS = (NN + 7) / 8;           // 12500

    // CSR + dinv (shared by all 3 layers)
    cudaMemsetAsync(cnt, 0, NN * sizeof(int));
    k_edges<<<EDGE_BLKS, TB>>>(ei);
    k_scanA<<<NBLK, SCAN_B>>>();
    k_scanC<<<NBLK, SCAN_B>>>();

    // CSR fill + Layer-1 GEMM (independent, one kernel)
    k_fill_gemm1<<<EDGE_BLKS + GEMM_BLKS, TB>>>(ei, EDGE_BLKS, x, W1, hA);

    // Layer 1 aggregate + Layer 2 GEMM: hB = dinv * (relu(agg(hA)+b1) @ W2)
    k_agg_gemm<32, 64><<<NN * 8 / TB, TB>>>(hA, hB, b1, W2);    // 3125 blocks

    // Layer 2 aggregate + Layer 3 GEMM: hA = dinv * (relu(agg(hB)+b2) @ W3)
    k_agg_gemm<64, 64><<<NN * 16 / TB, TB>>>(hB, hA, b2, W3);   // 6250 blocks

    // Layer 3 aggregate + b3 + row L2-normalize -> out
    k_agg_final<<<NN * 16 / TB, TB>>>(hA, b3, out);             // 6250 blocks
}

// round 8
// speedup vs baseline: 1.3083x; 1.1020x over previous
#include <cuda_runtime.h>
#include <stdint.h>

#define NN 100000
#define NE 1200000
#define SCAN_B 1024
#define NBLK ((NN + SCAN_B - 1) / SCAN_B)   // 98

// ---------------- scratch (device globals: allocation-free) ----------------
__device__ __align__(128) float g_hA[NN * 64];    // h ping
__device__ __align__(128) float g_hB[NN * 64];    // h pong
__device__ __align__(128) float g_dinv[NN];
__device__ __align__(128) int   g_cnt[NN];        // in-degree (excl. self)
__device__ __align__(128) int   g_rowptr[NN + 1];
__device__ __align__(128) int   g_wpos[NN];
__device__ __align__(128) int   g_src[NE];        // CSR: sources grouped by dst
__device__ __align__(128) int   g_tmp[NN];
__device__ __align__(128) int   g_bsum[NBLK];

// ---------------- per-block int64 probe (ei L2-cached => free) -------------
// int64 little-endian node ids < 2^31 => every odd int32 word of the first 64
// is zero; astronomically unlikely for random int32 ids.
__device__ __forceinline__ int probe_is64(const int* ei) {
    int az = 1;
#pragma unroll
    for (int j = 0; j < 32; j++) az &= (ei[2 * j + 1] == 0);
    return az;
}

// ---------------- count in-degrees (g_cnt pre-zeroed via memset) -----------
__global__ void k_edges(const int* __restrict__ ei) {
    __shared__ int s_is64;
    if (threadIdx.x == 0) s_is64 = probe_is64(ei);
    __syncthreads();
    int e = blockIdx.x * blockDim.x + threadIdx.x;
    if (e < NE) {
        int c = ei[(size_t)(NE + e) * (s_is64 ? 2 : 1)];
        c = min(max(c, 0), NN - 1);
        atomicAdd(&g_cnt[c], 1);
    }
}

// ---------------- scan pass A: block-local inclusive scan ------------------
__global__ void k_scanA() {
    __shared__ int sm[SCAN_B];
    int i = blockIdx.x * SCAN_B + threadIdx.x;
    int v = (i < NN) ? g_cnt[i] : 0;
    sm[threadIdx.x] = v;
    __syncthreads();
    for (int off = 1; off < SCAN_B; off <<= 1) {
        int t = (threadIdx.x >= off) ? sm[threadIdx.x - off] : 0;
        __syncthreads();
        sm[threadIdx.x] += t;
        __syncthreads();
    }
    if (i < NN) g_tmp[i] = sm[threadIdx.x];
    if (threadIdx.x == SCAN_B - 1) g_bsum[blockIdx.x] = sm[threadIdx.x];
}

// ---------------- scan pass B: inline block-sum scan + finalize ------------
__global__ void k_scanC() {
    __shared__ int bs[128];
    if (threadIdx.x < 128)
        bs[threadIdx.x] = (threadIdx.x < NBLK) ? g_bsum[threadIdx.x] : 0;
    __syncthreads();
    for (int off = 1; off < 128; off <<= 1) {
        int t = (threadIdx.x >= off && threadIdx.x < 128) ? bs[threadIdx.x - off] : 0;
        __syncthreads();
        if (threadIdx.x < 128) bs[threadIdx.x] += t;
        __syncthreads();
    }
    int base = (blockIdx.x == 0) ? 0 : bs[blockIdx.x - 1];

    int i = blockIdx.x * SCAN_B + threadIdx.x;
    if (i < NN) {
        int inc = g_tmp[i] + base;
        g_rowptr[i + 1] = inc;
        g_wpos[i] = inc - g_cnt[i];
        g_dinv[i] = rsqrtf((float)(g_cnt[i] + 1));   // +1 self-loop
    }
    if (i == 0) g_rowptr[0] = 0;
}

// ---------------- fused: CSR fill  +  layer-1 GEMM -------------------------
// fill:  g_src[pos(col)] = row        (random atomics, latency-bound)
// gemm1: hA[n] = dinv[n]*(x[n]@W1)    8 threads/node, float4 LDG x, LDS.128 W.
__global__ void k_fill_gemm1(const int* __restrict__ ei, int fill_blocks,
                             const float* __restrict__ x,
                             const float* __restrict__ W,
                             float* __restrict__ hout) {
    if (blockIdx.x < fill_blocks) {
        __shared__ int s_is64;
        if (threadIdx.x == 0) s_is64 = probe_is64(ei);
        __syncthreads();
        int e = blockIdx.x * blockDim.x + threadIdx.x;
        if (e < NE) {
            int stride = s_is64 ? 2 : 1;
            int r = ei[(size_t)e * stride];
            int c = ei[(size_t)(NE + e) * stride];
            r = min(max(r, 0), NN - 1);
            c = min(max(c, 0), NN - 1);
            int pos = atomicAdd(&g_wpos[c], 1);
            g_src[pos] = r;
        }
        return;
    }

    // GEMM: DIN=64, DN=32, GRP=8 threads/node, CPT=4 cols/thread
    constexpr int XST = 68;                       // padded row stride (floats)
    __shared__ float Ws[64 * 32];
    __shared__ float xsh[8 * 4 * XST];            // 8 warps * 4 nodes/warp

    for (int i = threadIdx.x; i < 64 * 32; i += blockDim.x) Ws[i] = W[i];
    __syncthreads();

    const int t = (blockIdx.x - fill_blocks) * blockDim.x + threadIdx.x;
    const int n = t >> 3;                         // exact grid: n < NN always
    const int g = t & 7;

    const float4* __restrict__ x4 = reinterpret_cast<const float4*>(x);
    float4 xa = x4[n * 16 + g * 2];
    float4 xb = x4[n * 16 + g * 2 + 1];

    const int wid = threadIdx.x >> 5;
    const int nw  = (threadIdx.x & 31) >> 3;
    float* xrow = &xsh[(wid * 4 + nw) * XST];
    reinterpret_cast<float4*>(xrow)[g * 2]     = xa;
    reinterpret_cast<float4*>(xrow)[g * 2 + 1] = xb;
    __syncwarp();

    float out[4] = {0.f, 0.f, 0.f, 0.f};
    const float4* W4 = reinterpret_cast<const float4*>(Ws);
#pragma unroll
    for (int k4 = 0; k4 < 16; k4++) {
        float4 xk = reinterpret_cast<const float4*>(xrow)[k4];
#pragma unroll
        for (int kk = 0; kk < 4; kk++) {
            float xv = (&xk.x)[kk];
            float4 w = W4[(k4 * 4 + kk) * 8 + g];        // row k, cols g*4..g*4+3
            out[0] = fmaf(xv, w.x, out[0]);
            out[1] = fmaf(xv, w.y, out[1]);
            out[2] = fmaf(xv, w.z, out[2]);
            out[3] = fmaf(xv, w.w, out[3]);
        }
    }

    const float dn = g_dinv[n];
    float4 o;
    o.x = dn * out[0]; o.y = dn * out[1]; o.z = dn * out[2]; o.w = dn * out[3];
    reinterpret_cast<float4*>(hout)[n * 8 + g] = o;
}

// ---------------- fused aggregate + next-layer GEMM ------------------------
// o[n] = dinv[n]*(h[n] + sum_src h[src]); z = relu(o + bprev);
// hout[n] = dinv[n] * (z @ W).   GRP = HD/4 threads per node.
template <int HD, int DN>
__global__ void k_agg_gemm(const float* __restrict__ hin,
                           float* __restrict__ hout,
                           const float* __restrict__ bprev,
                           const float* __restrict__ W) {
    constexpr int GRP = HD / 4;          // threads per node (8 or 16)
    constexpr int NPW = 32 / GRP;        // nodes per warp
    constexpr int CPT = DN / GRP;        // output cols per thread (8 or 4)
    constexpr int XST = HD + 4;          // padded smem row stride (floats)

    __shared__ float Ws[HD * DN];
    __shared__ float xsh[8 * NPW * XST];

    for (int i = threadIdx.x; i < HD * DN; i += blockDim.x) Ws[i] = W[i];
    __syncthreads();

    const int t = blockIdx.x * blockDim.x + threadIdx.x;   // grid sized exactly
    const int n = t / GRP;
    const int g = t % GRP;

    const float4* __restrict__ h4 = reinterpret_cast<const float4*>(hin);

    // ---- gather (memory-bound): unroll 8 for MLP ----
    float4 acc = h4[n * GRP + g];                 // self term (h pre-scaled)
    int e = g_rowptr[n], end = g_rowptr[n + 1];
    for (; e + 8 <= end; e += 8) {
        int s[8];
#pragma unroll
        for (int u = 0; u < 8; u++) s[u] = g_src[e + u];
        float4 v[8];
#pragma unroll
        for (int u = 0; u < 8; u++) v[u] = h4[s[u] * GRP + g];
#pragma unroll
        for (int u = 0; u < 8; u++) {
            acc.x += v[u].x; acc.y += v[u].y; acc.z += v[u].z; acc.w += v[u].w;
        }
    }
    for (; e < end; e++) {
        float4 a = h4[g_src[e] * GRP + g];
        acc.x += a.x; acc.y += a.y; acc.z += a.z; acc.w += a.w;
    }

    const float dn = g_dinv[n];
    const float4 bp = reinterpret_cast<const float4*>(bprev)[g];
    float4 z;
    z.x = fmaxf(fmaf(dn, acc.x, bp.x), 0.0f);
    z.y = fmaxf(fmaf(dn, acc.y, bp.y), 0.0f);
    z.z = fmaxf(fmaf(dn, acc.z, bp.z), 0.0f);
    z.w = fmaxf(fmaf(dn, acc.w, bp.w), 0.0f);

    // ---- stage row in smem (warp-local), then GEMM (compute phase) ----
    const int wid = threadIdx.x >> 5;
    const int nw  = (threadIdx.x & 31) / GRP;
    float* xrow = &xsh[(wid * NPW + nw) * XST];
    reinterpret_cast<float4*>(xrow)[g] = z;
    __syncwarp();

    float out[CPT];
#pragma unroll
    for (int j = 0; j < CPT; j++) out[j] = 0.0f;

    const float4* W4 = reinterpret_cast<const float4*>(Ws);
#pragma unroll
    for (int k4 = 0; k4 < HD / 4; k4++) {
        float4 xk = reinterpret_cast<const float4*>(xrow)[k4];
#pragma unroll
        for (int kk = 0; kk < 4; kk++) {
            float xv = (&xk.x)[kk];
            const int kidx = k4 * 4 + kk;
#pragma unroll
            for (int j4 = 0; j4 < CPT / 4; j4++) {
                float4 w = W4[(kidx * DN + g * CPT) / 4 + j4];
                out[j4 * 4 + 0] = fmaf(xv, w.x, out[j4 * 4 + 0]);
                out[j4 * 4 + 1] = fmaf(xv, w.y, out[j4 * 4 + 1]);
                out[j4 * 4 + 2] = fmaf(xv, w.z, out[j4 * 4 + 2]);
                out[j4 * 4 + 3] = fmaf(xv, w.w, out[j4 * 4 + 3]);
            }
        }
    }

#pragma unroll
    for (int j = 0; j < CPT; j += 4) {
        float4 o;
        o.x = dn * out[j];     o.y = dn * out[j + 1];
        o.z = dn * out[j + 2]; o.w = dn * out[j + 3];
        reinterpret_cast<float4*>(hout)[(n * DN + g * CPT + j) >> 2] = o;
    }
}

// ---------------- fused aggregate + bias + row L2-normalize ----------------
__global__ void k_agg_final(const float* __restrict__ hin,
                            const float* __restrict__ b3,
                            float* __restrict__ out) {
    const int t = blockIdx.x * blockDim.x + threadIdx.x;
    const int n = t >> 4;          // GRP = 16
    const int g = t & 15;

    const float4* __restrict__ h4 = reinterpret_cast<const float4*>(hin);

    float4 acc = h4[n * 16 + g];
    int e = g_rowptr[n], end = g_rowptr[n + 1];
    for (; e + 8 <= end; e += 8) {
        int s[8];
#pragma unroll
        for (int u = 0; u < 8; u++) s[u] = g_src[e + u];
        float4 v[8];
#pragma unroll
        for (int u = 0; u < 8; u++) v[u] = h4[s[u] * 16 + g];
#pragma unroll
        for (int u = 0; u < 8; u++) {
            acc.x += v[u].x; acc.y += v[u].y; acc.z += v[u].z; acc.w += v[u].w;
        }
    }
    for (; e < end; e++) {
        float4 a = h4[g_src[e] * 16 + g];
        acc.x += a.x; acc.y += a.y; acc.z += a.z; acc.w += a.w;
    }

    const float dn = g_dinv[n];
    const float4 bp = reinterpret_cast<const float4*>(b3)[g];
    float4 v;
    v.x = fmaf(dn, acc.x, bp.x);
    v.y = fmaf(dn, acc.y, bp.y);
    v.z = fmaf(dn, acc.z, bp.z);
    v.w = fmaf(dn, acc.w, bp.w);

    float s = v.x * v.x + v.y * v.y + v.z * v.z + v.w * v.w;
    s += __shfl_xor_sync(0xffffffffu, s, 1);
    s += __shfl_xor_sync(0xffffffffu, s, 2);
    s += __shfl_xor_sync(0xffffffffu, s, 4);
    s += __shfl_xor_sync(0xffffffffu, s, 8);
    float inv = 1.0f / fmaxf(sqrtf(s), 1e-12f);

    float4 o;
    o.x = v.x * inv; o.y = v.y * inv; o.z = v.z * inv; o.w = v.w * inv;
    reinterpret_cast<float4*>(out)[n * 16 + g] = o;
}

// ---------------- launch ----------------
extern "C" void kernel_launch(void* const* d_in, const int* in_sizes, int n_in,
                              void* d_out, int out_size) {
    const float* x  = (const float*)d_in[0];
    const int*   ei = (const int*)d_in[1];   // int32 (JAX x64 off) or int64 via probe
    const float* W1 = (const float*)d_in[2];
    const float* b1 = (const float*)d_in[3];
    const float* W2 = (const float*)d_in[4];
    const float* b2 = (const float*)d_in[5];
    const float* W3 = (const float*)d_in[6];
    const float* b3 = (const float*)d_in[7];
    float* out = (float*)d_out;

    float *hA, *hB;
    cudaGetSymbolAddress((void**)&hA, g_hA);
    cudaGetSymbolAddress((void**)&hB, g_hB);
    int* cnt;
    cudaGetSymbolAddress((void**)&cnt, g_cnt);

    const int TB = 256;
    const int EDGE_BLKS = (NE + TB - 1) / TB;     // 4688
    const int G1_BLKS   = NN * 8 / TB;            // 3125 (exact)

    // CSR + dinv (shared by all 3 layers)
    cudaMemsetAsync(cnt, 0, NN * sizeof(int));
    k_edges<<<EDGE_BLKS, TB>>>(ei);
    k_scanA<<<NBLK, SCAN_B>>>();
    k_scanC<<<NBLK, SCAN_B>>>();

    // CSR fill + Layer-1 GEMM (independent, one kernel)
    k_fill_gemm1<<<EDGE_BLKS + G1_BLKS, TB>>>(ei, EDGE_BLKS, x, W1, hA);

    // Layer 1 aggregate + Layer 2 GEMM: hB = dinv * (relu(agg(hA)+b1) @ W2)
    k_agg_gemm<32, 64><<<NN * 8 / TB, TB>>>(hA, hB, b1, W2);    // 3125 blocks

    // Layer 2 aggregate + Layer 3 GEMM: hA = dinv * (relu(agg(hB)+b2) @ W3)
    k_agg_gemm<64, 64><<<NN * 16 / TB, TB>>>(hB, hA, b2, W3);   // 6250 blocks

    // Layer 3 aggregate + b3 + row L2-normalize -> out
    k_agg_final<<<NN * 16 / TB, TB>>>(hA, b3, out);             // 6250 blocks
}

// round 10
// speedup vs baseline: 1.5975x; 1.2211x over previous
#include <cuda_runtime.h>
#include <stdint.h>

#define NN 100000
#define NE 1200000
#define SCAN_B 1024
#define NBLK ((NN + SCAN_B - 1) / SCAN_B)   // 98

// ---------------- scratch (device globals: allocation-free) ----------------
__device__ __align__(128) float g_hA[NN * 64];    // h ping
__device__ __align__(128) float g_hB[NN * 64];    // h pong
__device__ __align__(128) float g_dinv[NN];
__device__ __align__(128) int   g_cnt[NN];        // in-degree (excl. self)
__device__ __align__(128) int   g_rowptr[NN + 1];
__device__ __align__(128) int   g_wpos[NN];
__device__ __align__(128) int   g_src[NE];        // CSR: sources grouped by dst
__device__ __align__(128) int   g_tmp[NN];
__device__ __align__(128) int   g_bsum[NBLK];

// ---------------- per-block int64 probe (ei L2-cached => free) -------------
__device__ __forceinline__ int probe_is64(const int* ei) {
    int az = 1;
#pragma unroll
    for (int j = 0; j < 32; j++) az &= (ei[2 * j + 1] == 0);
    return az;
}

// ---------------- count in-degrees, 2 edges/thread (g_cnt pre-zeroed) ------
__global__ void k_edges(const int* __restrict__ ei) {
    __shared__ int s_is64;
    if (threadIdx.x == 0) s_is64 = probe_is64(ei);
    __syncthreads();
    int stride = s_is64 ? 2 : 1;
    int e0 = (blockIdx.x * blockDim.x + threadIdx.x) * 2;
    if (e0 < NE) {
        int c0 = ei[(size_t)(NE + e0) * stride];
        c0 = min(max(c0, 0), NN - 1);
        int c1 = -1;
        if (e0 + 1 < NE) {
            c1 = ei[(size_t)(NE + e0 + 1) * stride];
            c1 = min(max(c1, 0), NN - 1);
        }
        atomicAdd(&g_cnt[c0], 1);
        if (c1 >= 0) atomicAdd(&g_cnt[c1], 1);
    }
}

// ---------------- scan pass A: block-local inclusive scan ------------------
__global__ void k_scanA() {
    __shared__ int sm[SCAN_B];
    int i = blockIdx.x * SCAN_B + threadIdx.x;
    int v = (i < NN) ? g_cnt[i] : 0;
    sm[threadIdx.x] = v;
    __syncthreads();
    for (int off = 1; off < SCAN_B; off <<= 1) {
        int t = (threadIdx.x >= off) ? sm[threadIdx.x - off] : 0;
        __syncthreads();
        sm[threadIdx.x] += t;
        __syncthreads();
    }
    if (i < NN) g_tmp[i] = sm[threadIdx.x];
    if (threadIdx.x == SCAN_B - 1) g_bsum[blockIdx.x] = sm[threadIdx.x];
}

// ---------------- scan pass B: inline block-sum scan + finalize ------------
__global__ void k_scanC() {
    __shared__ int bs[128];
    if (threadIdx.x < 128)
        bs[threadIdx.x] = (threadIdx.x < NBLK) ? g_bsum[threadIdx.x] : 0;
    __syncthreads();
    for (int off = 1; off < 128; off <<= 1) {
        int t = (threadIdx.x >= off && threadIdx.x < 128) ? bs[threadIdx.x - off] : 0;
        __syncthreads();
        if (threadIdx.x < 128) bs[threadIdx.x] += t;
        __syncthreads();
    }
    int base = (blockIdx.x == 0) ? 0 : bs[blockIdx.x - 1];

    int i = blockIdx.x * SCAN_B + threadIdx.x;
    if (i < NN) {
        int inc = g_tmp[i] + base;
        g_rowptr[i + 1] = inc;
        g_wpos[i] = inc - g_cnt[i];
        g_dinv[i] = rsqrtf((float)(g_cnt[i] + 1));   // +1 self-loop
    }
    if (i == 0) g_rowptr[0] = 0;
}

// ---------------- fused: CSR fill (2 edges/thread) + layer-1 GEMM ----------
// gemm1: block stages 32 x-rows in smem; compute remap: lane=node, warp=cols.
// W read once per block (0.25KB/node of smem traffic).
__global__ void k_fill_gemm1(const int* __restrict__ ei, int fill_blocks,
                             const float* __restrict__ x,
                             const float* __restrict__ W,
                             float* __restrict__ hout) {
    if (blockIdx.x < fill_blocks) {
        __shared__ int s_is64;
        if (threadIdx.x == 0) s_is64 = probe_is64(ei);
        __syncthreads();
        int stride = s_is64 ? 2 : 1;
        int e0 = (blockIdx.x * blockDim.x + threadIdx.x) * 2;
        if (e0 < NE) {
            int r0 = ei[(size_t)e0 * stride];
            int c0 = ei[(size_t)(NE + e0) * stride];
            r0 = min(max(r0, 0), NN - 1);
            c0 = min(max(c0, 0), NN - 1);
            int r1 = -1, c1 = -1;
            if (e0 + 1 < NE) {
                r1 = ei[(size_t)(e0 + 1) * stride];
                c1 = ei[(size_t)(NE + e0 + 1) * stride];
                r1 = min(max(r1, 0), NN - 1);
                c1 = min(max(c1, 0), NN - 1);
            }
            int p0 = atomicAdd(&g_wpos[c0], 1);
            int p1 = (c1 >= 0) ? atomicAdd(&g_wpos[c1], 1) : 0;
            g_src[p0] = r0;
            if (c1 >= 0) g_src[p1] = r1;
        }
        return;
    }

    // ---- gemm1: DIN=64, DN=32, 32 nodes/block ----
    __shared__ float Ws[64 * 32];                 // 8KB
    __shared__ float xsh[32 * 68];                // 32 rows, XST=68 (16B-aligned)
    __shared__ float dsh[32];

    for (int i = threadIdx.x; i < 64 * 32; i += blockDim.x) Ws[i] = W[i];

    const int n0 = (blockIdx.x - fill_blocks) * 32;
    const float4* __restrict__ xg = reinterpret_cast<const float4*>(x);
    for (int i = threadIdx.x; i < 512; i += blockDim.x) {      // 32 rows * 16 f4
        int row = i >> 4, fi = i & 15;
        reinterpret_cast<float4*>(xsh + row * 68)[fi] = xg[(size_t)(n0 + row) * 16 + fi];
    }
    if (threadIdx.x < 32) dsh[threadIdx.x] = g_dinv[n0 + threadIdx.x];
    __syncthreads();

    const int l = threadIdx.x & 31;               // node (local)
    const int w = threadIdx.x >> 5;               // col-quad (0..7)
    const float* xr = xsh + l * 68;
    const float4* W4 = reinterpret_cast<const float4*>(Ws);

    float a0 = 0.f, a1 = 0.f, a2 = 0.f, a3 = 0.f;
#pragma unroll
    for (int k4 = 0; k4 < 16; k4++) {
        float4 xk = reinterpret_cast<const float4*>(xr)[k4];
#pragma unroll
        for (int kk = 0; kk < 4; kk++) {
            float xv = (&xk.x)[kk];
            float4 wv = W4[(k4 * 4 + kk) * 8 + w];
            a0 = fmaf(xv, wv.x, a0);
            a1 = fmaf(xv, wv.y, a1);
            a2 = fmaf(xv, wv.z, a2);
            a3 = fmaf(xv, wv.w, a3);
        }
    }
    float dn = dsh[l];
    float4 o; o.x = dn * a0; o.y = dn * a1; o.z = dn * a2; o.w = dn * a3;
    reinterpret_cast<float4*>(hout)[(size_t)(n0 + l) * 8 + w] = o;
}

// ---------------- layer-1 agg + layer-2 GEMM (HD=32 -> DN=64) --------------
// Gather: 8 threads/node, 32 nodes/block. Compute: lane=node, warp=col-octet.
__global__ void k_agg_gemm2(const float* __restrict__ hin,
                            float* __restrict__ hout,
                            const float* __restrict__ bprev,
                            const float* __restrict__ W) {
    __shared__ float Ws[32 * 64];                 // 8KB
    __shared__ float xsh[32 * 36];                // 32 z-rows, XST=36
    __shared__ float dsh[32];

    for (int i = threadIdx.x; i < 32 * 64; i += blockDim.x) Ws[i] = W[i];

    const int t = blockIdx.x * blockDim.x + threadIdx.x;
    const int n = t >> 3;
    const int g = t & 7;
    const int nw = threadIdx.x >> 3;

    const float4* __restrict__ h4 = reinterpret_cast<const float4*>(hin);

    float4 acc = h4[n * 8 + g];                   // self term
    int e = g_rowptr[n], end = g_rowptr[n + 1];
    for (; e + 8 <= end; e += 8) {
        int s[8];
#pragma unroll
        for (int u = 0; u < 8; u++) s[u] = g_src[e + u];
        float4 v[8];
#pragma unroll
        for (int u = 0; u < 8; u++) v[u] = h4[s[u] * 8 + g];
#pragma unroll
        for (int u = 0; u < 8; u++) {
            acc.x += v[u].x; acc.y += v[u].y; acc.z += v[u].z; acc.w += v[u].w;
        }
    }
    for (; e < end; e++) {
        float4 a = h4[g_src[e] * 8 + g];
        acc.x += a.x; acc.y += a.y; acc.z += a.z; acc.w += a.w;
    }

    const float dn = g_dinv[n];
    const float4 bp = reinterpret_cast<const float4*>(bprev)[g];
    float4 z;
    z.x = fmaxf(fmaf(dn, acc.x, bp.x), 0.0f);
    z.y = fmaxf(fmaf(dn, acc.y, bp.y), 0.0f);
    z.z = fmaxf(fmaf(dn, acc.z, bp.z), 0.0f);
    z.w = fmaxf(fmaf(dn, acc.w, bp.w), 0.0f);
    reinterpret_cast<float4*>(xsh + nw * 36)[g] = z;
    if (g == 0) dsh[nw] = dn;
    __syncthreads();

    // compute: node = lane, cols = warp*8 .. warp*8+7
    const int l = threadIdx.x & 31;
    const int w = threadIdx.x >> 5;
    const float* xr = xsh + l * 36;
    const float4* W4 = reinterpret_cast<const float4*>(Ws);

    float a[8];
#pragma unroll
    for (int j = 0; j < 8; j++) a[j] = 0.f;
#pragma unroll
    for (int k4 = 0; k4 < 8; k4++) {
        float4 xk = reinterpret_cast<const float4*>(xr)[k4];
#pragma unroll
        for (int kk = 0; kk < 4; kk++) {
            float xv = (&xk.x)[kk];
            int k = k4 * 4 + kk;
            float4 w0 = W4[k * 16 + w * 2];
            float4 w1 = W4[k * 16 + w * 2 + 1];
            a[0] = fmaf(xv, w0.x, a[0]); a[1] = fmaf(xv, w0.y, a[1]);
            a[2] = fmaf(xv, w0.z, a[2]); a[3] = fmaf(xv, w0.w, a[3]);
            a[4] = fmaf(xv, w1.x, a[4]); a[5] = fmaf(xv, w1.y, a[5]);
            a[6] = fmaf(xv, w1.z, a[6]); a[7] = fmaf(xv, w1.w, a[7]);
        }
    }
    const float dn2 = dsh[l];
    const int n2 = blockIdx.x * 32 + l;
    float4 o0, o1;
    o0.x = dn2 * a[0]; o0.y = dn2 * a[1]; o0.z = dn2 * a[2]; o0.w = dn2 * a[3];
    o1.x = dn2 * a[4]; o1.y = dn2 * a[5]; o1.z = dn2 * a[6]; o1.w = dn2 * a[7];
    reinterpret_cast<float4*>(hout)[(size_t)n2 * 16 + w * 2]     = o0;
    reinterpret_cast<float4*>(hout)[(size_t)n2 * 16 + w * 2 + 1] = o1;
}

// ---------------- layer-2 agg + layer-3 GEMM (HD=64 -> DN=64) --------------
// Gather: 16 threads/node, 16 nodes/block. Compute: half-lane=node, q=col-quad.
__global__ void k_agg_gemm3(const float* __restrict__ hin,
                            float* __restrict__ hout,
                            const float* __restrict__ bprev,
                            const float* __restrict__ W) {
    __shared__ float Ws[64 * 64];                 // 16KB
    __shared__ float xsh[16 * 68];                // 16 z-rows, XST=68
    __shared__ float dsh[16];

    for (int i = threadIdx.x; i < 64 * 64; i += blockDim.x) Ws[i] = W[i];

    const int t = blockIdx.x * blockDim.x + threadIdx.x;
    const int n = t >> 4;
    const int g = t & 15;
    const int nw = threadIdx.x >> 4;

    const float4* __restrict__ h4 = reinterpret_cast<const float4*>(hin);

    float4 acc = h4[n * 16 + g];
    int e = g_rowptr[n], end = g_rowptr[n + 1];
    for (; e + 8 <= end; e += 8) {
        int s[8];
#pragma unroll
        for (int u = 0; u < 8; u++) s[u] = g_src[e + u];
        float4 v[8];
#pragma unroll
        for (int u = 0; u < 8; u++) v[u] = h4[s[u] * 16 + g];
#pragma unroll
        for (int u = 0; u < 8; u++) {
            acc.x += v[u].x; acc.y += v[u].y; acc.z += v[u].z; acc.w += v[u].w;
        }
    }
    for (; e < end; e++) {
        float4 a = h4[g_src[e] * 16 + g];
        acc.x += a.x; acc.y += a.y; acc.z += a.z; acc.w += a.w;
    }

    const float dn = g_dinv[n];
    const float4 bp = reinterpret_cast<const float4*>(bprev)[g];
    float4 z;
    z.x = fmaxf(fmaf(dn, acc.x, bp.x), 0.0f);
    z.y = fmaxf(fmaf(dn, acc.y, bp.y), 0.0f);
    z.z = fmaxf(fmaf(dn, acc.z, bp.z), 0.0f);
    z.w = fmaxf(fmaf(dn, acc.w, bp.w), 0.0f);
    reinterpret_cast<float4*>(xsh + nw * 68)[g] = z;
    if (g == 0) dsh[nw] = dn;
    __syncthreads();

    // compute: nl = lane&15, q = warp*2 + (lane>>4)
    const int l  = threadIdx.x & 31;
    const int w  = threadIdx.x >> 5;
    const int nl = l & 15;
    const int q  = w * 2 + (l >> 4);
    const float* xr = xsh + nl * 68;
    const float4* W4 = reinterpret_cast<const float4*>(Ws);

    float a0 = 0.f, a1 = 0.f, a2 = 0.f, a3 = 0.f;
#pragma unroll
    for (int k4 = 0; k4 < 16; k4++) {
        float4 xk = reinterpret_cast<const float4*>(xr)[k4];
#pragma unroll
        for (int kk = 0; kk < 4; kk++) {
            float xv = (&xk.x)[kk];
            float4 wv = W4[(k4 * 4 + kk) * 16 + q];
            a0 = fmaf(xv, wv.x, a0);
            a1 = fmaf(xv, wv.y, a1);
            a2 = fmaf(xv, wv.z, a2);
            a3 = fmaf(xv, wv.w, a3);
        }
    }
    const float dn2 = dsh[nl];
    const int n2 = blockIdx.x * 16 + nl;
    float4 o; o.x = dn2 * a0; o.y = dn2 * a1; o.z = dn2 * a2; o.w = dn2 * a3;
    reinterpret_cast<float4*>(hout)[(size_t)n2 * 16 + q] = o;
}

// ---------------- fused aggregate + bias + row L2-normalize ----------------
__global__ void k_agg_final(const float* __restrict__ hin,
                            const float* __restrict__ b3,
                            float* __restrict__ out) {
    const int t = blockIdx.x * blockDim.x + threadIdx.x;
    const int n = t >> 4;          // GRP = 16
    const int g = t & 15;

    const float4* __restrict__ h4 = reinterpret_cast<const float4*>(hin);

    float4 acc = h4[n * 16 + g];
    int e = g_rowptr[n], end = g_rowptr[n + 1];
    for (; e + 8 <= end; e += 8) {
        int s[8];
#pragma unroll
        for (int u = 0; u < 8; u++) s[u] = g_src[e + u];
        float4 v[8];
#pragma unroll
        for (int u = 0; u < 8; u++) v[u] = h4[s[u] * 16 + g];
#pragma unroll
        for (int u = 0; u < 8; u++) {
            acc.x += v[u].x; acc.y += v[u].y; acc.z += v[u].z; acc.w += v[u].w;
        }
    }
    for (; e < end; e++) {
        float4 a = h4[g_src[e] * 16 + g];
        acc.x += a.x; acc.y += a.y; acc.z += a.z; acc.w += a.w;
    }

    const float dn = g_dinv[n];
    const float4 bp = reinterpret_cast<const float4*>(b3)[g];
    float4 v;
    v.x = fmaf(dn, acc.x, bp.x);
    v.y = fmaf(dn, acc.y, bp.y);
    v.z = fmaf(dn, acc.z, bp.z);
    v.w = fmaf(dn, acc.w, bp.w);

    float s = v.x * v.x + v.y * v.y + v.z * v.z + v.w * v.w;
    s += __shfl_xor_sync(0xffffffffu, s, 1);
    s += __shfl_xor_sync(0xffffffffu, s, 2);
    s += __shfl_xor_sync(0xffffffffu, s, 4);
    s += __shfl_xor_sync(0xffffffffu, s, 8);
    float inv = 1.0f / fmaxf(sqrtf(s), 1e-12f);

    float4 o;
    o.x = v.x * inv; o.y = v.y * inv; o.z = v.z * inv; o.w = v.w * inv;
    reinterpret_cast<float4*>(out)[n * 16 + g] = o;
}

// ---------------- launch ----------------
extern "C" void kernel_launch(void* const* d_in, const int* in_sizes, int n_in,
                              void* d_out, int out_size) {
    const float* x  = (const float*)d_in[0];
    const int*   ei = (const int*)d_in[1];   // int32 (JAX x64 off) or int64 via probe
    const float* W1 = (const float*)d_in[2];
    const float* b1 = (const float*)d_in[3];
    const float* W2 = (const float*)d_in[4];
    const float* b2 = (const float*)d_in[5];
    const float* W3 = (const float*)d_in[6];
    const float* b3 = (const float*)d_in[7];
    float* out = (float*)d_out;

    float *hA, *hB;
    cudaGetSymbolAddress((void**)&hA, g_hA);
    cudaGetSymbolAddress((void**)&hB, g_hB);
    int* cnt;
    cudaGetSymbolAddress((void**)&cnt, g_cnt);

    const int TB = 256;
    const int EDGE2_BLKS = (NE / 2 + TB - 1) / TB;   // 2344 (2 edges/thread)
    const int G1_BLKS    = NN / 32;                  // 3125 (32 nodes/block)

    // CSR + dinv (shared by all 3 layers)
    cudaMemsetAsync(cnt, 0, NN * sizeof(int));
    k_edges<<<EDGE2_BLKS, TB>>>(ei);
    k_scanA<<<NBLK, SCAN_B>>>();
    k_scanC<<<NBLK, SCAN_B>>>();

    // CSR fill + Layer-1 GEMM (independent, one kernel)
    k_fill_gemm1<<<EDGE2_BLKS + G1_BLKS, TB>>>(ei, EDGE2_BLKS, x, W1, hA);

    // Layer 1 aggregate + Layer 2 GEMM: hB = dinv * (relu(agg(hA)+b1) @ W2)
    k_agg_gemm2<<<NN / 32, TB>>>(hA, hB, b1, W2);    // 3125 blocks
    // Layer 2 aggregate + Layer 3 GEMM: hA = dinv * (relu(agg(hB)+b2) @ W3)
    k_agg_gemm3<<<NN / 16, TB>>>(hB, hA, b2, W3);    // 6250 blocks
    // Layer 3 aggregate + b3 + row L2-normalize -> out
    k_agg_final<<<NN * 16 / TB, TB>>>(hA, b3, out);  // 6250 blocks
}